// round 4
// baseline (speedup 1.0000x reference)
#include <cuda_runtime.h>
#include <math.h>

#define BB 32
#define NN 16384
#define KK 64
#define CHUNKS 16
#define ROWS_PER_CHUNK (NN / CHUNKS)   // 1024
#define BLOCKS_PER_BATCH (CHUNKS * 2)  // 32

// Deterministic scratch: [tensor][b][chunk][k][4]  (sg, sx, sy, sz)
__device__ float g_partials[2 * BB * CHUNKS * KK * 4];
// Per-batch arrival counters (reset by finalizer -> graph-replay safe)
__device__ int g_count[BB];

__device__ __forceinline__ void warp_reduce_n(float* v, int n)
{
    for (int o = 16; o; o >>= 1)
        for (int j = 0; j < n; ++j)
            v[j] += __shfl_xor_sync(0xffffffffu, v[j], o);
}

// ---------------------------------------------------------------------------
// Fused kernel: per-chunk weighted reductions (HBM streaming) + last-block
// finalize (chunk reduction -> weighted Procrustes -> 3x3 SVD -> R,t).
// ---------------------------------------------------------------------------
__global__ void __launch_bounds__(256, 8) fused_kernel(
    const float* __restrict__ pts_x, const float* __restrict__ pts_y,
    const float* __restrict__ gam_x, const float* __restrict__ gam_y,
    float* __restrict__ out)
{
    const int chunk = blockIdx.x;
    const int b     = blockIdx.y;
    const int tsel  = blockIdx.z;
    const float* __restrict__ pts = tsel ? pts_y : pts_x;
    const float* __restrict__ gam = tsel ? gam_y : gam_x;

    const int tid = threadIdx.x;
    const int kg  = tid & 15;   // k4 group
    const int rg  = tid >> 4;   // row group 0..15

    float sg[4] = {0.f, 0.f, 0.f, 0.f};
    float sx[4] = {0.f, 0.f, 0.f, 0.f};
    float sy[4] = {0.f, 0.f, 0.f, 0.f};
    float sz[4] = {0.f, 0.f, 0.f, 0.f};

    const int n0 = chunk * ROWS_PER_CHUNK;

    #pragma unroll 4
    for (int r = rg; r < ROWS_PER_CHUNK; r += 16) {
        const size_t n = (size_t)b * NN + (size_t)(n0 + r);
        // gamma is streamed once: evict-first so it never thrashes L2
        const float4 g = __ldcs(reinterpret_cast<const float4*>(gam + n * KK + 4 * kg));
        const float px = __ldg(pts + n * 3 + 0);
        const float py = __ldg(pts + n * 3 + 1);
        const float pz = __ldg(pts + n * 3 + 2);
        sg[0] += g.x; sg[1] += g.y; sg[2] += g.z; sg[3] += g.w;
        sx[0] = fmaf(g.x, px, sx[0]); sx[1] = fmaf(g.y, px, sx[1]);
        sx[2] = fmaf(g.z, px, sx[2]); sx[3] = fmaf(g.w, px, sx[3]);
        sy[0] = fmaf(g.x, py, sy[0]); sy[1] = fmaf(g.y, py, sy[1]);
        sy[2] = fmaf(g.z, py, sy[2]); sy[3] = fmaf(g.w, py, sy[3]);
        sz[0] = fmaf(g.x, pz, sz[0]); sz[1] = fmaf(g.y, pz, sz[1]);
        sz[2] = fmaf(g.z, pz, sz[2]); sz[3] = fmaf(g.w, pz, sz[3]);
    }

    // Block reduction across the 16 row-groups: smem[rg][k][val]
    __shared__ float smem[16 * KK * 4];
    #pragma unroll
    for (int j = 0; j < 4; ++j) {
        const int kk = 4 * kg + j;
        float* p = &smem[(rg * KK + kk) * 4];
        p[0] = sg[j]; p[1] = sx[j]; p[2] = sy[j]; p[3] = sz[j];
    }
    __syncthreads();

    // 256 threads == 64 k * 4 vals; tid = k*4 + val
    {
        const int kk  = tid >> 2;
        const int val = tid & 3;
        float acc = 0.f;
        #pragma unroll
        for (int r = 0; r < 16; ++r) acc += smem[(r * KK + kk) * 4 + val];
        g_partials[(((size_t)tsel * BB + b) * CHUNKS + chunk) * (KK * 4) + tid] = acc;
    }

    // ---- arrival: last block of this batch finalizes ----
    __shared__ int isLast;
    __threadfence();                       // make partials visible device-wide
    __syncthreads();                       // all warps' STGs issued before arrive
    if (tid == 0) {
        const int old = atomicAdd(&g_count[b], 1);
        isLast = (old == BLOCKS_PER_BATCH - 1);
    }
    __syncthreads();
    if (!isLast) return;

    // =======================================================================
    // Finalize (runs on exactly one block per batch; partials are L2-warm)
    // =======================================================================
    const int k    = tid;          // 0..255, only k<64 active in reductions
    const int wid  = tid >> 5;
    const int lane = tid & 31;

    __shared__ float wsum[2][9];
    __shared__ float bc[8];

    float w = 0.f, mux[3] = {0, 0, 0}, muy[3] = {0, 0, 0};
    if (k < KK) {
        float sgx = 0.f, sxx = 0.f, syx = 0.f, szx = 0.f;
        float sgy = 0.f, sxy = 0.f, syy = 0.f, szy = 0.f;
        #pragma unroll
        for (int c = 0; c < CHUNKS; ++c) {
            const float4 px = __ldcg(reinterpret_cast<const float4*>(
                &g_partials[(((size_t)0 * BB + b) * CHUNKS + c) * (KK * 4) + k * 4]));
            sgx += px.x; sxx += px.y; syx += px.z; szx += px.w;
            const float4 py = __ldcg(reinterpret_cast<const float4*>(
                &g_partials[(((size_t)1 * BB + b) * CHUNKS + c) * (KK * 4) + k * 4]));
            sgy += py.x; sxy += py.y; syy += py.z; szy += py.w;
        }
        const float EPSf = 1e-8f;
        const float pix = sgx * (1.0f / (float)NN);
        const float piy = sgy * (1.0f / (float)NN);
        const float rpx = __fdividef(1.0f, pix + EPSf);
        const float rpy = __fdividef(1.0f, piy + EPSf);
        mux[0] = sxx * rpx; mux[1] = syx * rpx; mux[2] = szx * rpx;
        muy[0] = sxy * rpy; muy[1] = syy * rpy; muy[2] = szy * rpy;
        w = pix * piy;

        // --- Reduction 1: weighted centroids (7 values) ---
        float v[7] = { w, w * mux[0], w * mux[1], w * mux[2],
                          w * muy[0], w * muy[1], w * muy[2] };
        warp_reduce_n(v, 7);
        if (lane == 0)
            #pragma unroll
            for (int j = 0; j < 7; ++j) wsum[wid][j] = v[j];
    }
    __syncthreads();
    if (tid == 0) {
        const float ws = __fdividef(1.0f, wsum[0][0] + wsum[1][0] + 1e-8f);
        #pragma unroll
        for (int j = 0; j < 6; ++j)
            bc[j] = (wsum[0][j + 1] + wsum[1][j + 1]) * ws;   // c_s then c_t
    }
    __syncthreads();

    // --- Reduction 2: weighted covariance H (9 values) ---
    if (k < KK) {
        const float s0 = mux[0] - bc[0], s1 = mux[1] - bc[1], s2 = mux[2] - bc[2];
        const float t0 = muy[0] - bc[3], t1 = muy[1] - bc[4], t2 = muy[2] - bc[5];
        float v[9] = { w * s0 * t0, w * s0 * t1, w * s0 * t2,
                       w * s1 * t0, w * s1 * t1, w * s1 * t2,
                       w * s2 * t0, w * s2 * t1, w * s2 * t2 };
        warp_reduce_n(v, 9);
        if (lane == 0)
            #pragma unroll
            for (int j = 0; j < 9; ++j) wsum[wid][j] = v[j];
    }
    __syncthreads();

    if (tid == 0) {
        float H[3][3];
        #pragma unroll
        for (int i = 0; i < 3; ++i)
            #pragma unroll
            for (int j = 0; j < 3; ++j)
                H[i][j] = wsum[0][i * 3 + j] + wsum[1][i * 3 + j];

        // Scale H to O(1) so fp32 HtH Jacobi has healthy relative precision.
        float hmax = 0.f;
        for (int i = 0; i < 3; ++i)
            for (int j = 0; j < 3; ++j) hmax = fmaxf(hmax, fabsf(H[i][j]));
        const float hscale = (hmax > 1e-30f) ? __fdividef(1.0f, hmax) : 1.0f;
        float Hs[3][3];
        for (int i = 0; i < 3; ++i)
            for (int j = 0; j < 3; ++j) Hs[i][j] = H[i][j] * hscale;

        // A = Hs^T Hs (symmetric)
        float A[3][3];
        for (int i = 0; i < 3; ++i)
            for (int j = 0; j < 3; ++j)
                A[i][j] = Hs[0][i] * Hs[0][j] + Hs[1][i] * Hs[1][j] + Hs[2][i] * Hs[2][j];

        float V[3][3] = {{1, 0, 0}, {0, 1, 0}, {0, 0, 1}};
        // Cyclic Jacobi, 6 sweeps (quadratic convergence; fp32 noise by ~4)
        #pragma unroll 1
        for (int sweep = 0; sweep < 6; ++sweep) {
            const int PQ[3][2] = {{0, 1}, {0, 2}, {1, 2}};
            #pragma unroll
            for (int m = 0; m < 3; ++m) {
                const int p = PQ[m][0], q = PQ[m][1];
                const float apq = A[p][q];
                if (fabsf(apq) < 1e-35f) continue;
                const float tau = __fdividef(A[q][q] - A[p][p], 2.0f * apq);
                const float tt  = __fdividef(copysignf(1.0f, tau),
                                  fabsf(tau) + sqrtf(1.0f + tau * tau));
                const float c = rsqrtf(1.0f + tt * tt);
                const float s = tt * c;
                const float app = A[p][p], aqq = A[q][q];
                A[p][p] = app - tt * apq;
                A[q][q] = aqq + tt * apq;
                A[p][q] = A[q][p] = 0.0f;
                const int r = 3 - p - q;
                const float arp = A[r][p], arq = A[r][q];
                A[r][p] = A[p][r] = c * arp - s * arq;
                A[r][q] = A[q][r] = s * arp + c * arq;
                #pragma unroll
                for (int i = 0; i < 3; ++i) {
                    const float vip = V[i][p], viq = V[i][q];
                    V[i][p] = c * vip - s * viq;
                    V[i][q] = s * vip + c * viq;
                }
            }
        }

        float eig[3] = {A[0][0], A[1][1], A[2][2]};
        // Sort descending, permuting V columns
        #pragma unroll
        for (int i = 0; i < 2; ++i)
            #pragma unroll
            for (int j = i + 1; j < 3; ++j)
                if (eig[j] > eig[i]) {
                    float tmp = eig[i]; eig[i] = eig[j]; eig[j] = tmp;
                    for (int r = 0; r < 3; ++r) {
                        tmp = V[r][i]; V[r][i] = V[r][j]; V[r][j] = tmp;
                    }
                }

        // U columns: u0 = normalize(Hs v0); u1 = GS(Hs v1); u2 = u0 x u1
        float U[3][3];
        {
            float u0[3], u1[3];
            for (int i = 0; i < 3; ++i)
                u0[i] = Hs[i][0] * V[0][0] + Hs[i][1] * V[1][0] + Hs[i][2] * V[2][0];
            const float nn0 = u0[0] * u0[0] + u0[1] * u0[1] + u0[2] * u0[2];
            if (nn0 > 1e-40f) { const float r = rsqrtf(nn0); u0[0] *= r; u0[1] *= r; u0[2] *= r; }
            else { u0[0] = 1; u0[1] = 0; u0[2] = 0; }

            for (int i = 0; i < 3; ++i)
                u1[i] = Hs[i][0] * V[0][1] + Hs[i][1] * V[1][1] + Hs[i][2] * V[2][1];
            const float d01 = u1[0] * u0[0] + u1[1] * u0[1] + u1[2] * u0[2];
            u1[0] -= d01 * u0[0]; u1[1] -= d01 * u0[1]; u1[2] -= d01 * u0[2];
            const float nn1 = u1[0] * u1[0] + u1[1] * u1[1] + u1[2] * u1[2];
            if (nn1 > 1e-40f) { const float r = rsqrtf(nn1); u1[0] *= r; u1[1] *= r; u1[2] *= r; }
            else {
                const float ax = fabsf(u0[0]), ay = fabsf(u0[1]), az = fabsf(u0[2]);
                float e[3] = {0, 0, 0};
                if (ax <= ay && ax <= az) e[0] = 1;
                else if (ay <= az) e[1] = 1;
                else e[2] = 1;
                u1[0] = u0[1] * e[2] - u0[2] * e[1];
                u1[1] = u0[2] * e[0] - u0[0] * e[2];
                u1[2] = u0[0] * e[1] - u0[1] * e[0];
                const float rn = rsqrtf(u1[0] * u1[0] + u1[1] * u1[1] + u1[2] * u1[2]);
                u1[0] *= rn; u1[1] *= rn; u1[2] *= rn;
            }
            const float u2[3] = { u0[1] * u1[2] - u0[2] * u1[1],
                                  u0[2] * u1[0] - u0[0] * u1[2],
                                  u0[0] * u1[1] - u0[1] * u1[0] };
            for (int i = 0; i < 3; ++i) {
                U[i][0] = u0[i]; U[i][1] = u1[i]; U[i][2] = u2[i];
            }
        }

        const float detV =
            V[0][0] * (V[1][1] * V[2][2] - V[1][2] * V[2][1]) -
            V[0][1] * (V[1][0] * V[2][2] - V[1][2] * V[2][0]) +
            V[0][2] * (V[1][0] * V[2][1] - V[1][1] * V[2][0]);
        const float detU =
            U[0][0] * (U[1][1] * U[2][2] - U[1][2] * U[2][1]) -
            U[0][1] * (U[1][0] * U[2][2] - U[1][2] * U[2][0]) +
            U[0][2] * (U[1][0] * U[2][1] - U[1][1] * U[2][0]);
        const float d = detV * detU;   // det(V U^T)

        // R = V diag(1,1,d) U^T
        float R[3][3];
        for (int i = 0; i < 3; ++i)
            for (int j = 0; j < 3; ++j)
                R[i][j] = V[i][0] * U[j][0] + V[i][1] * U[j][1] + d * V[i][2] * U[j][2];

        // t = c_t - R c_s
        float tv[3];
        for (int i = 0; i < 3; ++i)
            tv[i] = bc[3 + i] - (R[i][0] * bc[0] + R[i][1] * bc[1] + R[i][2] * bc[2]);

        // Output: R (B*9) then t (B*3)
        for (int i = 0; i < 3; ++i)
            for (int j = 0; j < 3; ++j)
                out[b * 9 + i * 3 + j] = R[i][j];
        for (int i = 0; i < 3; ++i)
            out[BB * 9 + b * 3 + i] = tv[i];

        // Reset counter for next graph replay (all 32 arrivals already in)
        g_count[b] = 0;
    }
}

extern "C" void kernel_launch(void* const* d_in, const int* in_sizes, int n_in,
                              void* d_out, int out_size)
{
    const float* pts_x = (const float*)d_in[0];
    const float* pts_y = (const float*)d_in[1];
    const float* gam_x = (const float*)d_in[2];
    const float* gam_y = (const float*)d_in[3];

    dim3 grid(CHUNKS, BB, 2);
    fused_kernel<<<grid, 256>>>(pts_x, pts_y, gam_x, gam_y, (float*)d_out);
}

// round 5
// speedup vs baseline: 1.1445x; 1.1445x over previous
#include <cuda_runtime.h>
#include <math.h>

#define BB 32
#define NN 16384
#define KK 64
#define CHUNKS 16
#define ROWS_PER_CHUNK (NN / CHUNKS)   // 1024

// Deterministic scratch: [tensor][b][chunk][k][4]  (sg, sx, sy, sz)
__device__ float g_partials[2 * BB * CHUNKS * KK * 4];

// ---------------------------------------------------------------------------
// Stage 1: per-chunk weighted reductions (pure HBM streaming).
// Block = 256 threads: kg = tid&15 owns k in [4*kg, 4*kg+3] (one LDG.128/row),
// rg = tid>>4 strides rows. Fully coalesced gamma reads (1KB per block-row).
// launch_bounds(256,6): ~42 regs, 48 warps/SM — no spills, deep MLP.
// ---------------------------------------------------------------------------
__global__ void __launch_bounds__(256, 6) stage1_kernel(
    const float* __restrict__ pts_x, const float* __restrict__ pts_y,
    const float* __restrict__ gam_x, const float* __restrict__ gam_y)
{
    const int chunk = blockIdx.x;
    const int b     = blockIdx.y;
    const int tsel  = blockIdx.z;
    const float* __restrict__ pts = tsel ? pts_y : pts_x;
    const float* __restrict__ gam = tsel ? gam_y : gam_x;

    const int tid = threadIdx.x;
    const int kg  = tid & 15;   // k4 group
    const int rg  = tid >> 4;   // row group 0..15

    float sg[4] = {0.f, 0.f, 0.f, 0.f};
    float sx[4] = {0.f, 0.f, 0.f, 0.f};
    float sy[4] = {0.f, 0.f, 0.f, 0.f};
    float sz[4] = {0.f, 0.f, 0.f, 0.f};

    const int n0 = chunk * ROWS_PER_CHUNK;

    #pragma unroll 8
    for (int r = rg; r < ROWS_PER_CHUNK; r += 16) {
        const size_t n = (size_t)b * NN + (size_t)(n0 + r);
        // gamma is streamed once: evict-first so it never thrashes L2
        const float4 g = __ldcs(reinterpret_cast<const float4*>(gam + n * KK + 4 * kg));
        const float px = __ldg(pts + n * 3 + 0);
        const float py = __ldg(pts + n * 3 + 1);
        const float pz = __ldg(pts + n * 3 + 2);
        sg[0] += g.x; sg[1] += g.y; sg[2] += g.z; sg[3] += g.w;
        sx[0] = fmaf(g.x, px, sx[0]); sx[1] = fmaf(g.y, px, sx[1]);
        sx[2] = fmaf(g.z, px, sx[2]); sx[3] = fmaf(g.w, px, sx[3]);
        sy[0] = fmaf(g.x, py, sy[0]); sy[1] = fmaf(g.y, py, sy[1]);
        sy[2] = fmaf(g.z, py, sy[2]); sy[3] = fmaf(g.w, py, sy[3]);
        sz[0] = fmaf(g.x, pz, sz[0]); sz[1] = fmaf(g.y, pz, sz[1]);
        sz[2] = fmaf(g.z, pz, sz[2]); sz[3] = fmaf(g.w, pz, sz[3]);
    }

    // Block reduction across the 16 row-groups: smem[rg][k][val]
    __shared__ float smem[16 * KK * 4];
    #pragma unroll
    for (int j = 0; j < 4; ++j) {
        const int k = 4 * kg + j;
        float* p = &smem[(rg * KK + k) * 4];
        p[0] = sg[j]; p[1] = sx[j]; p[2] = sy[j]; p[3] = sz[j];
    }
    __syncthreads();

    // 256 threads == 64 k * 4 vals; tid = k*4 + val
    const int k   = tid >> 2;
    const int val = tid & 3;
    float acc = 0.f;
    #pragma unroll
    for (int r = 0; r < 16; ++r) acc += smem[(r * KK + k) * 4 + val];

    g_partials[(((size_t)tsel * BB + b) * CHUNKS + chunk) * (KK * 4) + tid] = acc;
}

// ---------------------------------------------------------------------------
// Stage 2: chunk reduction + weighted Procrustes + 3x3 SVD, all fp32.
// One block per batch, 64 threads (one per k). Launched with PDL so its
// setup overlaps stage1's tail; cudaGridDependencySynchronize() gates reads.
// ---------------------------------------------------------------------------
__device__ __forceinline__ void warp_reduce_n(float* v, int n)
{
    for (int o = 16; o; o >>= 1)
        for (int j = 0; j < n; ++j)
            v[j] += __shfl_xor_sync(0xffffffffu, v[j], o);
}

__global__ void __launch_bounds__(64) stage2_kernel(float* __restrict__ out)
{
    // PDL: wait until stage1 (the prior grid) has fully completed.
    cudaGridDependencySynchronize();

    const int b    = blockIdx.x;
    const int k    = threadIdx.x;   // 0..63
    const int wid  = k >> 5;
    const int lane = k & 31;

    float sgx = 0.f, sxx = 0.f, syx = 0.f, szx = 0.f;
    float sgy = 0.f, sxy = 0.f, syy = 0.f, szy = 0.f;
    #pragma unroll
    for (int c = 0; c < CHUNKS; ++c) {
        const float4 px = __ldcg(reinterpret_cast<const float4*>(
            &g_partials[(((size_t)0 * BB + b) * CHUNKS + c) * (KK * 4) + k * 4]));
        sgx += px.x; sxx += px.y; syx += px.z; szx += px.w;
        const float4 py = __ldcg(reinterpret_cast<const float4*>(
            &g_partials[(((size_t)1 * BB + b) * CHUNKS + c) * (KK * 4) + k * 4]));
        sgy += py.x; sxy += py.y; syy += py.z; szy += py.w;
    }

    const float EPSf = 1e-8f;
    const float pix = sgx * (1.0f / (float)NN);
    const float piy = sgy * (1.0f / (float)NN);
    const float rpx = __fdividef(1.0f, pix + EPSf);
    const float rpy = __fdividef(1.0f, piy + EPSf);
    float mux[3] = { sxx * rpx, syx * rpx, szx * rpx };
    float muy[3] = { sxy * rpy, syy * rpy, szy * rpy };
    const float w = pix * piy;

    __shared__ float wsum[2][9];
    __shared__ float bc[8];

    // --- Reduction 1: weighted centroids (7 values) ---
    {
        float v[7] = { w, w * mux[0], w * mux[1], w * mux[2],
                          w * muy[0], w * muy[1], w * muy[2] };
        warp_reduce_n(v, 7);
        if (lane == 0)
            #pragma unroll
            for (int j = 0; j < 7; ++j) wsum[wid][j] = v[j];
    }
    __syncthreads();
    if (k == 0) {
        const float ws = __fdividef(1.0f, wsum[0][0] + wsum[1][0] + EPSf);
        #pragma unroll
        for (int j = 0; j < 6; ++j)
            bc[j] = (wsum[0][j + 1] + wsum[1][j + 1]) * ws;   // c_s then c_t
    }
    __syncthreads();

    // --- Reduction 2: weighted covariance H (9 values) ---
    const float s0 = mux[0] - bc[0], s1 = mux[1] - bc[1], s2 = mux[2] - bc[2];
    const float t0 = muy[0] - bc[3], t1 = muy[1] - bc[4], t2 = muy[2] - bc[5];
    {
        float v[9] = { w * s0 * t0, w * s0 * t1, w * s0 * t2,
                       w * s1 * t0, w * s1 * t1, w * s1 * t2,
                       w * s2 * t0, w * s2 * t1, w * s2 * t2 };
        warp_reduce_n(v, 9);
        if (lane == 0)
            #pragma unroll
            for (int j = 0; j < 9; ++j) wsum[wid][j] = v[j];
    }
    __syncthreads();

    if (k == 0) {
        float H[3][3];
        #pragma unroll
        for (int i = 0; i < 3; ++i)
            #pragma unroll
            for (int j = 0; j < 3; ++j)
                H[i][j] = wsum[0][i * 3 + j] + wsum[1][i * 3 + j];

        // Scale H to O(1) so fp32 HtH Jacobi has healthy relative precision.
        float hmax = 0.f;
        for (int i = 0; i < 3; ++i)
            for (int j = 0; j < 3; ++j) hmax = fmaxf(hmax, fabsf(H[i][j]));
        const float hscale = (hmax > 1e-30f) ? __fdividef(1.0f, hmax) : 1.0f;
        float Hs[3][3];
        for (int i = 0; i < 3; ++i)
            for (int j = 0; j < 3; ++j) Hs[i][j] = H[i][j] * hscale;

        // A = Hs^T Hs (symmetric)
        float A[3][3];
        for (int i = 0; i < 3; ++i)
            for (int j = 0; j < 3; ++j)
                A[i][j] = Hs[0][i] * Hs[0][j] + Hs[1][i] * Hs[1][j] + Hs[2][i] * Hs[2][j];

        float V[3][3] = {{1, 0, 0}, {0, 1, 0}, {0, 0, 1}};
        // Cyclic Jacobi, 6 sweeps (quadratic convergence; fp32 noise by ~4)
        #pragma unroll 1
        for (int sweep = 0; sweep < 6; ++sweep) {
            const int PQ[3][2] = {{0, 1}, {0, 2}, {1, 2}};
            #pragma unroll
            for (int m = 0; m < 3; ++m) {
                const int p = PQ[m][0], q = PQ[m][1];
                const float apq = A[p][q];
                if (fabsf(apq) < 1e-35f) continue;
                const float tau = __fdividef(A[q][q] - A[p][p], 2.0f * apq);
                const float tt  = __fdividef(copysignf(1.0f, tau),
                                  fabsf(tau) + sqrtf(1.0f + tau * tau));
                const float c = rsqrtf(1.0f + tt * tt);
                const float s = tt * c;
                const float app = A[p][p], aqq = A[q][q];
                A[p][p] = app - tt * apq;
                A[q][q] = aqq + tt * apq;
                A[p][q] = A[q][p] = 0.0f;
                const int r = 3 - p - q;
                const float arp = A[r][p], arq = A[r][q];
                A[r][p] = A[p][r] = c * arp - s * arq;
                A[r][q] = A[q][r] = s * arp + c * arq;
                #pragma unroll
                for (int i = 0; i < 3; ++i) {
                    const float vip = V[i][p], viq = V[i][q];
                    V[i][p] = c * vip - s * viq;
                    V[i][q] = s * vip + c * viq;
                }
            }
        }

        float eig[3] = {A[0][0], A[1][1], A[2][2]};
        // Sort descending, permuting V columns
        #pragma unroll
        for (int i = 0; i < 2; ++i)
            #pragma unroll
            for (int j = i + 1; j < 3; ++j)
                if (eig[j] > eig[i]) {
                    float tmp = eig[i]; eig[i] = eig[j]; eig[j] = tmp;
                    for (int r = 0; r < 3; ++r) {
                        tmp = V[r][i]; V[r][i] = V[r][j]; V[r][j] = tmp;
                    }
                }

        // U columns: u0 = normalize(Hs v0); u1 = GS(Hs v1); u2 = u0 x u1
        float U[3][3];
        {
            float u0[3], u1[3];
            for (int i = 0; i < 3; ++i)
                u0[i] = Hs[i][0] * V[0][0] + Hs[i][1] * V[1][0] + Hs[i][2] * V[2][0];
            const float nn0 = u0[0] * u0[0] + u0[1] * u0[1] + u0[2] * u0[2];
            if (nn0 > 1e-40f) { const float r = rsqrtf(nn0); u0[0] *= r; u0[1] *= r; u0[2] *= r; }
            else { u0[0] = 1; u0[1] = 0; u0[2] = 0; }

            for (int i = 0; i < 3; ++i)
                u1[i] = Hs[i][0] * V[0][1] + Hs[i][1] * V[1][1] + Hs[i][2] * V[2][1];
            const float d01 = u1[0] * u0[0] + u1[1] * u0[1] + u1[2] * u0[2];
            u1[0] -= d01 * u0[0]; u1[1] -= d01 * u0[1]; u1[2] -= d01 * u0[2];
            const float nn1 = u1[0] * u1[0] + u1[1] * u1[1] + u1[2] * u1[2];
            if (nn1 > 1e-40f) { const float r = rsqrtf(nn1); u1[0] *= r; u1[1] *= r; u1[2] *= r; }
            else {
                // pick any unit vector orthogonal to u0
                const float ax = fabsf(u0[0]), ay = fabsf(u0[1]), az = fabsf(u0[2]);
                float e[3] = {0, 0, 0};
                if (ax <= ay && ax <= az) e[0] = 1;
                else if (ay <= az) e[1] = 1;
                else e[2] = 1;
                u1[0] = u0[1] * e[2] - u0[2] * e[1];
                u1[1] = u0[2] * e[0] - u0[0] * e[2];
                u1[2] = u0[0] * e[1] - u0[1] * e[0];
                const float rn = rsqrtf(u1[0] * u1[0] + u1[1] * u1[1] + u1[2] * u1[2]);
                u1[0] *= rn; u1[1] *= rn; u1[2] *= rn;
            }
            const float u2[3] = { u0[1] * u1[2] - u0[2] * u1[1],
                                  u0[2] * u1[0] - u0[0] * u1[2],
                                  u0[0] * u1[1] - u0[1] * u1[0] };
            for (int i = 0; i < 3; ++i) {
                U[i][0] = u0[i]; U[i][1] = u1[i]; U[i][2] = u2[i];
            }
        }

        const float detV =
            V[0][0] * (V[1][1] * V[2][2] - V[1][2] * V[2][1]) -
            V[0][1] * (V[1][0] * V[2][2] - V[1][2] * V[2][0]) +
            V[0][2] * (V[1][0] * V[2][1] - V[1][1] * V[2][0]);
        const float detU =
            U[0][0] * (U[1][1] * U[2][2] - U[1][2] * U[2][1]) -
            U[0][1] * (U[1][0] * U[2][2] - U[1][2] * U[2][0]) +
            U[0][2] * (U[1][0] * U[2][1] - U[1][1] * U[2][0]);
        const float d = detV * detU;   // det(V U^T)

        // R = V diag(1,1,d) U^T
        float R[3][3];
        for (int i = 0; i < 3; ++i)
            for (int j = 0; j < 3; ++j)
                R[i][j] = V[i][0] * U[j][0] + V[i][1] * U[j][1] + d * V[i][2] * U[j][2];

        // t = c_t - R c_s
        float tv[3];
        for (int i = 0; i < 3; ++i)
            tv[i] = bc[3 + i] - (R[i][0] * bc[0] + R[i][1] * bc[1] + R[i][2] * bc[2]);

        // Output: R (B*9) then t (B*3)
        for (int i = 0; i < 3; ++i)
            for (int j = 0; j < 3; ++j)
                out[b * 9 + i * 3 + j] = R[i][j];
        for (int i = 0; i < 3; ++i)
            out[BB * 9 + b * 3 + i] = tv[i];
    }
}

extern "C" void kernel_launch(void* const* d_in, const int* in_sizes, int n_in,
                              void* d_out, int out_size)
{
    const float* pts_x = (const float*)d_in[0];
    const float* pts_y = (const float*)d_in[1];
    const float* gam_x = (const float*)d_in[2];
    const float* gam_y = (const float*)d_in[3];

    dim3 grid1(CHUNKS, BB, 2);
    stage1_kernel<<<grid1, 256>>>(pts_x, pts_y, gam_x, gam_y);

    // Stage 2 with programmatic dependent launch: overlaps launch setup with
    // stage1's tail; cudaGridDependencySynchronize() inside gates the reads.
    cudaLaunchConfig_t cfg = {};
    cfg.gridDim  = dim3(BB, 1, 1);
    cfg.blockDim = dim3(KK, 1, 1);
    cfg.stream   = 0;
    cudaLaunchAttribute attr[1];
    attr[0].id = cudaLaunchAttributeProgrammaticStreamSerialization;
    attr[0].val.programmaticStreamSerializationAllowed = 1;
    cfg.attrs    = attr;
    cfg.numAttrs = 1;
    float* outp = (float*)d_out;
    cudaError_t e = cudaLaunchKernelEx(&cfg, stage2_kernel, outp);
    if (e != cudaSuccess) {
        // Fallback: plain launch (still correct, just serialized)
        stage2_kernel<<<BB, KK>>>(outp);
    }
}

// round 7
// speedup vs baseline: 1.6127x; 1.4091x over previous
#include <cuda_runtime.h>
#include <math.h>

#define BB 32
#define NN 16384
#define KK 64
#define CHUNKS 16
#define ROWS_PER_CHUNK (NN / CHUNKS)   // 1024

// Deterministic scratch: [tensor][b][chunk][k][4]  (sg, sx, sy, sz)
__device__ float g_partials[2 * BB * CHUNKS * KK * 4];

// ---------------------------------------------------------------------------
// Stage 1: per-chunk weighted reductions (pure HBM streaming).
// R3-proven config: launch_bounds(256,8), unroll 4, __ldcs on gamma. DO NOT TOUCH.
// ---------------------------------------------------------------------------
__global__ void __launch_bounds__(256, 8) stage1_kernel(
    const float* __restrict__ pts_x, const float* __restrict__ pts_y,
    const float* __restrict__ gam_x, const float* __restrict__ gam_y)
{
    const int chunk = blockIdx.x;
    const int b     = blockIdx.y;
    const int tsel  = blockIdx.z;
    const float* __restrict__ pts = tsel ? pts_y : pts_x;
    const float* __restrict__ gam = tsel ? gam_y : gam_x;

    const int tid = threadIdx.x;
    const int kg  = tid & 15;   // k4 group
    const int rg  = tid >> 4;   // row group 0..15

    float sg[4] = {0.f, 0.f, 0.f, 0.f};
    float sx[4] = {0.f, 0.f, 0.f, 0.f};
    float sy[4] = {0.f, 0.f, 0.f, 0.f};
    float sz[4] = {0.f, 0.f, 0.f, 0.f};

    const int n0 = chunk * ROWS_PER_CHUNK;

    #pragma unroll 4
    for (int r = rg; r < ROWS_PER_CHUNK; r += 16) {
        const size_t n = (size_t)b * NN + (size_t)(n0 + r);
        // gamma is streamed once: evict-first so it never thrashes L2
        const float4 g = __ldcs(reinterpret_cast<const float4*>(gam + n * KK + 4 * kg));
        const float px = __ldg(pts + n * 3 + 0);
        const float py = __ldg(pts + n * 3 + 1);
        const float pz = __ldg(pts + n * 3 + 2);
        sg[0] += g.x; sg[1] += g.y; sg[2] += g.z; sg[3] += g.w;
        sx[0] = fmaf(g.x, px, sx[0]); sx[1] = fmaf(g.y, px, sx[1]);
        sx[2] = fmaf(g.z, px, sx[2]); sx[3] = fmaf(g.w, px, sx[3]);
        sy[0] = fmaf(g.x, py, sy[0]); sy[1] = fmaf(g.y, py, sy[1]);
        sy[2] = fmaf(g.z, py, sy[2]); sy[3] = fmaf(g.w, py, sy[3]);
        sz[0] = fmaf(g.x, pz, sz[0]); sz[1] = fmaf(g.y, pz, sz[1]);
        sz[2] = fmaf(g.z, pz, sz[2]); sz[3] = fmaf(g.w, pz, sz[3]);
    }

    // Block reduction across the 16 row-groups: smem[rg][k][val]
    __shared__ float smem[16 * KK * 4];
    #pragma unroll
    for (int j = 0; j < 4; ++j) {
        const int k = 4 * kg + j;
        float* p = &smem[(rg * KK + k) * 4];
        p[0] = sg[j]; p[1] = sx[j]; p[2] = sy[j]; p[3] = sz[j];
    }
    __syncthreads();

    // 256 threads == 64 k * 4 vals; tid = k*4 + val
    const int k   = tid >> 2;
    const int val = tid & 3;
    float acc = 0.f;
    #pragma unroll
    for (int r = 0; r < 16; ++r) acc += smem[(r * KK + k) * 4 + val];

    g_partials[(((size_t)tsel * BB + b) * CHUNKS + chunk) * (KK * 4) + tid] = acc;
}

// ---------------------------------------------------------------------------
// Stage 2: single-pass moment reduction + weighted Procrustes + 3x3 SVD.
// One block per batch, 64 threads. H = S_xy - wsum * c_s c_t^T (one reduction).
// ---------------------------------------------------------------------------
__device__ __forceinline__ void warp_reduce_n(float* v, int n)
{
    for (int o = 16; o; o >>= 1)
        for (int j = 0; j < n; ++j)
            v[j] += __shfl_xor_sync(0xffffffffu, v[j], o);
}

__global__ void __launch_bounds__(64) stage2_kernel(float* __restrict__ out)
{
    const int b    = blockIdx.x;
    const int k    = threadIdx.x;   // 0..63
    const int wid  = k >> 5;
    const int lane = k & 31;

    float sgx = 0.f, sxx = 0.f, syx = 0.f, szx = 0.f;
    float sgy = 0.f, sxy = 0.f, syy = 0.f, szy = 0.f;
    #pragma unroll
    for (int c = 0; c < CHUNKS; ++c) {
        const float4 px = __ldcg(reinterpret_cast<const float4*>(
            &g_partials[(((size_t)0 * BB + b) * CHUNKS + c) * (KK * 4) + k * 4]));
        sgx += px.x; sxx += px.y; syx += px.z; szx += px.w;
        const float4 py = __ldcg(reinterpret_cast<const float4*>(
            &g_partials[(((size_t)1 * BB + b) * CHUNKS + c) * (KK * 4) + k * 4]));
        sgy += py.x; sxy += py.y; syy += py.z; szy += py.w;
    }

    const float EPSf = 1e-8f;
    const float pix = sgx * (1.0f / (float)NN);
    const float piy = sgy * (1.0f / (float)NN);
    const float rpx = __fdividef(1.0f, pix + EPSf);
    const float rpy = __fdividef(1.0f, piy + EPSf);
    const float mux0 = sxx * rpx, mux1 = syx * rpx, mux2 = szx * rpx;
    const float muy0 = sxy * rpy, muy1 = syy * rpy, muy2 = szy * rpy;
    const float w = pix * piy;

    // --- Single-pass reduction: w, w*mux(3), w*muy(3), w*mux*muy^T(9) = 16 ---
    __shared__ float wsum[2][16];
    {
        float v[16] = {
            w,
            w * mux0, w * mux1, w * mux2,
            w * muy0, w * muy1, w * muy2,
            w * mux0 * muy0, w * mux0 * muy1, w * mux0 * muy2,
            w * mux1 * muy0, w * mux1 * muy1, w * mux1 * muy2,
            w * mux2 * muy0, w * mux2 * muy1, w * mux2 * muy2
        };
        warp_reduce_n(v, 16);
        if (lane == 0)
            #pragma unroll
            for (int j = 0; j < 16; ++j) wsum[wid][j] = v[j];
    }
    __syncthreads();

    if (k == 0) {
        float s[16];
        #pragma unroll
        for (int j = 0; j < 16; ++j) s[j] = wsum[0][j] + wsum[1][j];

        const float wtot = s[0];
        const float ws = __fdividef(1.0f, wtot + EPSf);
        const float cs[3] = { s[1] * ws, s[2] * ws, s[3] * ws };   // c_s
        const float ct[3] = { s[4] * ws, s[5] * ws, s[6] * ws };   // c_t

        // H = S_xy - wtot * c_s c_t^T
        float H[3][3];
        #pragma unroll
        for (int i = 0; i < 3; ++i)
            #pragma unroll
            for (int j = 0; j < 3; ++j)
                H[i][j] = s[7 + i * 3 + j] - wtot * cs[i] * ct[j];

        // Scale H to O(1) so fp32 HtH Jacobi has healthy relative precision.
        float hmax = 0.f;
        for (int i = 0; i < 3; ++i)
            for (int j = 0; j < 3; ++j) hmax = fmaxf(hmax, fabsf(H[i][j]));
        const float hscale = (hmax > 1e-30f) ? __fdividef(1.0f, hmax) : 1.0f;
        float Hs[3][3];
        for (int i = 0; i < 3; ++i)
            for (int j = 0; j < 3; ++j) Hs[i][j] = H[i][j] * hscale;

        // A = Hs^T Hs (symmetric)
        float A[3][3];
        for (int i = 0; i < 3; ++i)
            for (int j = 0; j < 3; ++j)
                A[i][j] = Hs[0][i] * Hs[0][j] + Hs[1][i] * Hs[1][j] + Hs[2][i] * Hs[2][j];

        float V[3][3] = {{1, 0, 0}, {0, 1, 0}, {0, 0, 1}};
        // Cyclic Jacobi, 5 sweeps. IEEE sqrtf: handles tau -> inf gracefully
        // (fast_sqrt(x)=x*rsqrtf(x) NaNs at x=inf — caused the R6 failure).
        #pragma unroll 1
        for (int sweep = 0; sweep < 5; ++sweep) {
            const int PQ[3][2] = {{0, 1}, {0, 2}, {1, 2}};
            #pragma unroll
            for (int m = 0; m < 3; ++m) {
                const int p = PQ[m][0], q = PQ[m][1];
                const float apq = A[p][q];
                if (fabsf(apq) < 1e-35f) continue;
                const float tau = __fdividef(A[q][q] - A[p][p], 2.0f * apq);
                float tt = __fdividef(copysignf(1.0f, tau),
                                      fabsf(tau) + sqrtf(1.0f + tau * tau));
                if (!isfinite(tt)) tt = 0.0f;
                const float c = rsqrtf(1.0f + tt * tt);
                const float s2 = tt * c;
                const float app = A[p][p], aqq = A[q][q];
                A[p][p] = app - tt * apq;
                A[q][q] = aqq + tt * apq;
                A[p][q] = A[q][p] = 0.0f;
                const int r = 3 - p - q;
                const float arp = A[r][p], arq = A[r][q];
                A[r][p] = A[p][r] = c * arp - s2 * arq;
                A[r][q] = A[q][r] = s2 * arp + c * arq;
                #pragma unroll
                for (int i = 0; i < 3; ++i) {
                    const float vip = V[i][p], viq = V[i][q];
                    V[i][p] = c * vip - s2 * viq;
                    V[i][q] = s2 * vip + c * viq;
                }
            }
        }

        float eig[3] = {A[0][0], A[1][1], A[2][2]};
        // Sort descending, permuting V columns
        #pragma unroll
        for (int i = 0; i < 2; ++i)
            #pragma unroll
            for (int j = i + 1; j < 3; ++j)
                if (eig[j] > eig[i]) {
                    float tmp = eig[i]; eig[i] = eig[j]; eig[j] = tmp;
                    for (int r = 0; r < 3; ++r) {
                        tmp = V[r][i]; V[r][i] = V[r][j]; V[r][j] = tmp;
                    }
                }

        // U columns: u0 = normalize(Hs v0); u1 = GS(Hs v1); u2 = u0 x u1
        float U[3][3];
        {
            float u0[3], u1[3];
            for (int i = 0; i < 3; ++i)
                u0[i] = Hs[i][0] * V[0][0] + Hs[i][1] * V[1][0] + Hs[i][2] * V[2][0];
            const float nn0 = u0[0] * u0[0] + u0[1] * u0[1] + u0[2] * u0[2];
            if (nn0 > 1e-40f) { const float r = rsqrtf(nn0); u0[0] *= r; u0[1] *= r; u0[2] *= r; }
            else { u0[0] = 1; u0[1] = 0; u0[2] = 0; }

            for (int i = 0; i < 3; ++i)
                u1[i] = Hs[i][0] * V[0][1] + Hs[i][1] * V[1][1] + Hs[i][2] * V[2][1];
            const float d01 = u1[0] * u0[0] + u1[1] * u0[1] + u1[2] * u0[2];
            u1[0] -= d01 * u0[0]; u1[1] -= d01 * u0[1]; u1[2] -= d01 * u0[2];
            const float nn1 = u1[0] * u1[0] + u1[1] * u1[1] + u1[2] * u1[2];
            if (nn1 > 1e-40f) { const float r = rsqrtf(nn1); u1[0] *= r; u1[1] *= r; u1[2] *= r; }
            else {
                // pick any unit vector orthogonal to u0
                const float ax = fabsf(u0[0]), ay = fabsf(u0[1]), az = fabsf(u0[2]);
                float e[3] = {0, 0, 0};
                if (ax <= ay && ax <= az) e[0] = 1;
                else if (ay <= az) e[1] = 1;
                else e[2] = 1;
                u1[0] = u0[1] * e[2] - u0[2] * e[1];
                u1[1] = u0[2] * e[0] - u0[0] * e[2];
                u1[2] = u0[0] * e[1] - u0[1] * e[0];
                const float rn = rsqrtf(u1[0] * u1[0] + u1[1] * u1[1] + u1[2] * u1[2]);
                u1[0] *= rn; u1[1] *= rn; u1[2] *= rn;
            }
            const float u2[3] = { u0[1] * u1[2] - u0[2] * u1[1],
                                  u0[2] * u1[0] - u0[0] * u1[2],
                                  u0[0] * u1[1] - u0[1] * u1[0] };
            for (int i = 0; i < 3; ++i) {
                U[i][0] = u0[i]; U[i][1] = u1[i]; U[i][2] = u2[i];
            }
        }

        const float detV =
            V[0][0] * (V[1][1] * V[2][2] - V[1][2] * V[2][1]) -
            V[0][1] * (V[1][0] * V[2][2] - V[1][2] * V[2][0]) +
            V[0][2] * (V[1][0] * V[2][1] - V[1][1] * V[2][0]);
        const float detU =
            U[0][0] * (U[1][1] * U[2][2] - U[1][2] * U[2][1]) -
            U[0][1] * (U[1][0] * U[2][2] - U[1][2] * U[2][0]) +
            U[0][2] * (U[1][0] * U[2][1] - U[1][1] * U[2][0]);
        const float d = detV * detU;   // det(V U^T)

        // R = V diag(1,1,d) U^T
        float R[3][3];
        for (int i = 0; i < 3; ++i)
            for (int j = 0; j < 3; ++j)
                R[i][j] = V[i][0] * U[j][0] + V[i][1] * U[j][1] + d * V[i][2] * U[j][2];

        // t = c_t - R c_s
        float tv[3];
        for (int i = 0; i < 3; ++i)
            tv[i] = ct[i] - (R[i][0] * cs[0] + R[i][1] * cs[1] + R[i][2] * cs[2]);

        // Output: R (B*9) then t (B*3)
        for (int i = 0; i < 3; ++i)
            for (int j = 0; j < 3; ++j)
                out[b * 9 + i * 3 + j] = R[i][j];
        for (int i = 0; i < 3; ++i)
            out[BB * 9 + b * 3 + i] = tv[i];
    }
}

extern "C" void kernel_launch(void* const* d_in, const int* in_sizes, int n_in,
                              void* d_out, int out_size)
{
    const float* pts_x = (const float*)d_in[0];
    const float* pts_y = (const float*)d_in[1];
    const float* gam_x = (const float*)d_in[2];
    const float* gam_y = (const float*)d_in[3];

    dim3 grid1(CHUNKS, BB, 2);
    stage1_kernel<<<grid1, 256>>>(pts_x, pts_y, gam_x, gam_y);
    stage2_kernel<<<BB, KK>>>((float*)d_out);
}